// round 4
// baseline (speedup 1.0000x reference)
#include <cuda_runtime.h>
#include <math.h>

// ---------------------------------------------------------------------------
// GraphConvolution (hyperbolic GCN layer), fp32 — fused pipeline:
//   1. k_gemm_fused: mx = x@W via f32x2 packed FMA (FFMA2), per-row ||x||
//      during float4 loads, in-register warp epilogue
//      (mobius_matvec scale + mobius_add(hb) + logmap0), zero accum rows.
//   2. k_spmm:  accum[row] += vals * tmp[col]   (float4 vector RED)
//   3. k_final: out = proj(expmap0(accum, c), c)
// ---------------------------------------------------------------------------

#define MAXN  50432
#define FOUT  64
#define MIN_NORM 1e-15f
#define BALL_EPS 4e-3f

typedef unsigned long long ull;

__device__ float g_tmp[MAXN * FOUT];
__device__ float g_accum[MAXN * FOUT];

__device__ __forceinline__ float warp_sum(float v) {
    #pragma unroll
    for (int o = 16; o > 0; o >>= 1) v += __shfl_xor_sync(0xffffffffu, v, o);
    return v;
}
// reduce across the 8 lanes of a lane-octet (lanes sharing tid>>3)
__device__ __forceinline__ float red8(float v) {
    v += __shfl_xor_sync(0xffffffffu, v, 1);
    v += __shfl_xor_sync(0xffffffffu, v, 2);
    v += __shfl_xor_sync(0xffffffffu, v, 4);
    return v;
}

// packed f32x2 helpers
__device__ __forceinline__ ull dup2(float x) {
    ull r; asm("mov.b64 %0, {%1, %1};" : "=l"(r) : "f"(x)); return r;
}
__device__ __forceinline__ void ffma2(ull& d, ull a, ull b) {
    asm("fma.rn.f32x2 %0, %1, %2, %0;" : "+l"(d) : "l"(a), "l"(b));
}
__device__ __forceinline__ float2 unpack2(ull v) {
    float2 f; asm("mov.b64 {%0, %1}, %2;" : "=f"(f.x), "=f"(f.y) : "l"(v)); return f;
}

// fast tanh / artanh (MUFU-backed); args clamped like the reference
__device__ __forceinline__ float tanh_fast(float x) {
    x = fminf(x, 15.0f);                   // x >= 0 in all our uses
    float e = __expf(2.0f * x);
    return (e - 1.0f) / (e + 1.0f);
}
__device__ __forceinline__ float artanh_fast(float v) {
    v = fminf(fmaxf(v, -1.0f + 1e-7f), 1.0f - 1e-7f);
    return 0.5f * __logf((1.0f + v) / (1.0f - v));
}

// --- 1. fused GEMM + row-wise epilogues --------------------------------------
#define BM 64
#define BN 64
#define BK 32
#define ASTRIDE 33   // As[row][k], odd stride -> conflict-free scalar stores

__global__ void __launch_bounds__(256)
k_gemm_fused(const float* __restrict__ X, const float* __restrict__ W,
             const float* __restrict__ bias, const float* __restrict__ cp,
             int N, int IN) {
    __shared__ float As[BM * ASTRIDE];     // [row][k]
    __shared__ float Bs[BK * BN];          // [k][col]
    __shared__ float s_xn[BM];
    __shared__ float s_hb[FOUT];
    __shared__ float s_y2;

    int tid  = threadIdx.x;                // 256 threads
    int lane = tid & 31;
    int wrp  = tid >> 5;
    int block_row = blockIdx.x * BM;
    int tx = tid & 7;                      // 8 col groups (8 cols each)
    int ty = tid >> 3;                     // 32 row groups (2 rows each)

    float c  = cp[0];
    float sc = sqrtf(c);

    // warp 0: hyperbolic bias hb = proj(expmap0(bias, c), c) and ||hb||^2
    if (wrp == 0) {
        float u0 = bias[lane], u1 = bias[lane + 32];
        float un = fmaxf(sqrtf(warp_sum(u0 * u0 + u1 * u1)), MIN_NORM);
        float scale = tanh_fast(sc * un) / (sc * un);
        float p0 = scale * u0, p1 = scale * u1;
        float pn = fmaxf(sqrtf(warp_sum(p0 * p0 + p1 * p1)), MIN_NORM);
        float maxn = (1.0f - BALL_EPS) / sc;
        float f = (pn > maxn) ? (maxn / pn) : 1.0f;
        s_hb[lane]      = p0 * f;
        s_hb[lane + 32] = p1 * f;
        if (lane == 0) {
            float hn = fminf(pn, maxn);
            s_y2 = hn * hn;
        }
    }

    ull acc[2][4];
    #pragma unroll
    for (int i = 0; i < 2; i++)
        #pragma unroll
        for (int j = 0; j < 4; j++) acc[i][j] = 0ull;

    float xsum[2] = {0.f, 0.f};            // ||x||^2 partials: rows tid>>3, tid>>3+32

    for (int k0 = 0; k0 < IN; k0 += BK) {
        // load X tile (64 rows x 32 k) as float4, transpose into As[row][k]
        #pragma unroll
        for (int i = 0; i < 2; i++) {
            int idx = tid + i * 256;       // 0..511
            int r   = idx >> 3;            // 0..63
            int c4  = idx & 7;             // float4 index within 32 k's
            int gr  = block_row + r;
            float4 v = (gr < N) ? *reinterpret_cast<const float4*>(X + (size_t)gr * IN + k0 + c4 * 4)
                                : make_float4(0.f, 0.f, 0.f, 0.f);
            float* a = As + r * ASTRIDE + c4 * 4;
            a[0] = v.x; a[1] = v.y; a[2] = v.z; a[3] = v.w;
            xsum[i] += v.x * v.x + v.y * v.y + v.z * v.z + v.w * v.w;
        }
        // load W tile (32 k x 64 cols) as float4
        #pragma unroll
        for (int i = 0; i < 2; i++) {
            int idx = tid + i * 256;
            int r   = idx >> 4;            // k row 0..31
            int c4  = idx & 15;
            *reinterpret_cast<float4*>(Bs + r * BN + c4 * 4) =
                *reinterpret_cast<const float4*>(W + (size_t)(k0 + r) * BN + c4 * 4);
        }
        __syncthreads();

        const float* arow0 = As + (ty * 2) * ASTRIDE;
        const float* arow1 = arow0 + ASTRIDE;
        #pragma unroll
        for (int k = 0; k < BK; k++) {
            union { float4 v; ull u[2]; } b0, b1;
            b0.v = *reinterpret_cast<const float4*>(Bs + k * BN + tx * 8);
            b1.v = *reinterpret_cast<const float4*>(Bs + k * BN + tx * 8 + 4);
            ull A0 = dup2(arow0[k]);
            ull A1 = dup2(arow1[k]);
            ffma2(acc[0][0], A0, b0.u[0]); ffma2(acc[0][1], A0, b0.u[1]);
            ffma2(acc[0][2], A0, b1.u[0]); ffma2(acc[0][3], A0, b1.u[1]);
            ffma2(acc[1][0], A1, b0.u[0]); ffma2(acc[1][1], A1, b0.u[1]);
            ffma2(acc[1][2], A1, b1.u[0]); ffma2(acc[1][3], A1, b1.u[1]);
        }
        __syncthreads();
    }

    // per-row ||x||: lanes sharing tid>>3 hold partials for rows tid>>3 (+32)
    #pragma unroll
    for (int i = 0; i < 2; i++) {
        float s = red8(xsum[i]);
        if ((lane & 7) == 0) s_xn[(tid >> 3) + 32 * i] = fmaxf(sqrtf(s), MIN_NORM);
    }

    // zero accumulator rows for this block (overlaps the barrier below)
    {
        float4 z = make_float4(0.f, 0.f, 0.f, 0.f);
        float4* ab = reinterpret_cast<float4*>(g_accum + (size_t)block_row * FOUT);
        int lim4 = ((N - block_row) < BM ? (N - block_row) : BM) * FOUT / 4;
        #pragma unroll
        for (int i = 0; i < (BM * FOUT / 4) / 256; i++) {
            int idx = tid + i * 256;
            if (idx < lim4) ab[idx] = z;
        }
    }
    __syncthreads();

    // epilogue, fully in registers: 2 rows/thread, each row spans one lane-octet
    float y2 = s_y2;
    float2 h[4];
    #pragma unroll
    for (int j = 0; j < 4; j++)
        h[j] = *reinterpret_cast<const float2*>(s_hb + tx * 8 + 2 * j);

    #pragma unroll
    for (int i = 0; i < 2; i++) {
        int r   = ty * 2 + i;
        int row = block_row + r;

        float2 m[4];
        #pragma unroll
        for (int j = 0; j < 4; j++) m[j] = unpack2(acc[i][j]);

        float smx = 0.f, sxh = 0.f;
        #pragma unroll
        for (int j = 0; j < 4; j++) {
            smx += m[j].x * m[j].x + m[j].y * m[j].y;
            sxh += m[j].x * h[j].x + m[j].y * h[j].y;
        }
        smx = red8(smx);                   // ||mx||^2
        sxh = red8(sxh);                   // mx . hb

        float x_n = s_xn[r];
        float mxn = fmaxf(sqrtf(smx), MIN_NORM);
        float at  = artanh_fast(sc * x_n);
        float scl = tanh_fast(mxn / x_n * at) / (mxn * sc);
        if (smx == 0.0f) scl = 0.0f;

        float x2 = scl * scl * smx;        // ||res||^2
        float xy = scl * sxh;              // res . hb

        float A = 1.0f + 2.0f * c * xy + c * y2;
        float B = 1.0f - c * x2;
        float den = fmaxf(1.0f + 2.0f * c * xy + c * c * x2 * y2, MIN_NORM);
        float inv_den = 1.0f / den;

        float2 a0[4];
        float pa = 0.f;
        #pragma unroll
        for (int j = 0; j < 4; j++) {
            a0[j].x = (A * (scl * m[j].x) + B * h[j].x) * inv_den;
            a0[j].y = (A * (scl * m[j].y) + B * h[j].y) * inv_den;
            pa += a0[j].x * a0[j].x + a0[j].y * a0[j].y;
        }
        pa = red8(pa);
        float pn = fmaxf(sqrtf(pa), MIN_NORM);
        float t = artanh_fast(sc * pn) / (sc * pn);

        if (row < N) {
            float* dst = g_tmp + (size_t)row * FOUT + tx * 8;
            *reinterpret_cast<float4*>(dst) =
                make_float4(t * a0[0].x, t * a0[0].y, t * a0[1].x, t * a0[1].y);
            *reinterpret_cast<float4*>(dst + 4) =
                make_float4(t * a0[2].x, t * a0[2].y, t * a0[3].x, t * a0[3].y);
        }
    }
}

// --- 2. SpMM: accum[row[e]] += vals[e] * tmp[col[e]] --------------------------
__global__ void k_spmm(const float* __restrict__ vals, const int* __restrict__ row,
                       const int* __restrict__ col, int E) {
    int g = blockIdx.x * blockDim.x + threadIdx.x;
    int e = g >> 4;
    int lane = g & 15;
    if (e >= E) return;
    int cc = __ldg(col + e);
    int rr = __ldg(row + e);
    float v = __ldg(vals + e);
    float4 t = *reinterpret_cast<const float4*>(g_tmp + (size_t)cc * FOUT + lane * 4);
    float4 a = make_float4(t.x * v, t.y * v, t.z * v, t.w * v);
    atomicAdd(reinterpret_cast<float4*>(g_accum + (size_t)rr * FOUT) + lane, a);
}

// --- 3. final: out = proj(expmap0(accum)) ------------------------------------
__global__ void k_final(const float* __restrict__ cp, float* __restrict__ out, int N) {
    int warp = (blockIdx.x * blockDim.x + threadIdx.x) >> 5;
    int lane = threadIdx.x & 31;
    if (warp >= N) return;
    float c = cp[0];
    float sc = sqrtf(c);
    size_t base = (size_t)warp * FOUT;
    float u0 = g_accum[base + lane];
    float u1 = g_accum[base + lane + 32];
    float un = fmaxf(sqrtf(warp_sum(u0 * u0 + u1 * u1)), MIN_NORM);
    float scale = tanh_fast(sc * un) / (sc * un);
    float p0 = scale * u0, p1 = scale * u1;
    float pn = fmaxf(sqrtf(warp_sum(p0 * p0 + p1 * p1)), MIN_NORM);
    float maxn = (1.0f - BALL_EPS) / sc;
    float f = (pn > maxn) ? (maxn / pn) : 1.0f;
    out[base + lane]      = p0 * f;
    out[base + lane + 32] = p1 * f;
}

// ---------------------------------------------------------------------------

extern "C" void kernel_launch(void* const* d_in, const int* in_sizes, int n_in,
                              void* d_out, int out_size) {
    const float* x    = (const float*)d_in[0];
    const float* w    = (const float*)d_in[1];
    const float* bias = (const float*)d_in[2];
    const float* vals = (const float*)d_in[3];
    const float* c    = (const float*)d_in[4];
    const int*   row  = (const int*)d_in[5];
    const int*   col  = (const int*)d_in[6];
    float* out = (float*)d_out;

    int OUT = in_sizes[2];               // 64
    int IN  = in_sizes[1] / OUT;         // 256
    int N   = in_sizes[0] / IN;          // 50000
    int E   = in_sizes[3];               // 800000
    (void)OUT; (void)n_in; (void)out_size;

    // 1. fused GEMM + epilogues (+ accumulator zeroing)
    k_gemm_fused<<<(N + BM - 1) / BM, 256>>>(x, w, bias, c, N, IN);

    // 2. SpMM scatter-add
    long long tot = (long long)E * 16;
    k_spmm<<<(int)((tot + 255) / 256), 256>>>(vals, row, col, E);

    // 3. final expmap0 + proj
    int rowBlocks = (N + 7) / 8;
    k_final<<<rowBlocks, 256>>>(c, out, N);
}

// round 5
// speedup vs baseline: 1.8993x; 1.8993x over previous
#include <cuda_runtime.h>
#include <math.h>
#include <stdint.h>

// ---------------------------------------------------------------------------
// GraphConvolution (hyperbolic GCN layer) — tf32 tensor-core GEMM + fused
// hyperbolic epilogue, float4-RED SpMM, expmap0+proj finisher.
//   1. k_gemm_fused: mx = x@W via mma.sync.m16n8k8.tf32, per-row ||x|| (fp32,
//      from raw loads), in-register mobius_matvec+mobius_add+logmap0, zero accum
//   2. k_spmm:  accum[row] += vals * tmp[col]   (float4 vector RED)
//   3. k_final: out = proj(expmap0(accum, c), c)
// ---------------------------------------------------------------------------

#define MAXN  50432
#define FOUT  64
#define MIN_NORM 1e-15f
#define BALL_EPS 4e-3f

__device__ float g_tmp[MAXN * FOUT];
__device__ float g_accum[MAXN * FOUT];

__device__ __forceinline__ float warp_sum(float v) {
    #pragma unroll
    for (int o = 16; o > 0; o >>= 1) v += __shfl_xor_sync(0xffffffffu, v, o);
    return v;
}
__device__ __forceinline__ float red8(float v) {
    v += __shfl_xor_sync(0xffffffffu, v, 1);
    v += __shfl_xor_sync(0xffffffffu, v, 2);
    v += __shfl_xor_sync(0xffffffffu, v, 4);
    return v;
}
__device__ __forceinline__ float red4(float v) {
    v += __shfl_xor_sync(0xffffffffu, v, 1);
    v += __shfl_xor_sync(0xffffffffu, v, 2);
    return v;
}

__device__ __forceinline__ float tanh_fast(float x) {
    x = fminf(x, 15.0f);                   // x >= 0 in all our uses
    float e = __expf(2.0f * x);
    return (e - 1.0f) / (e + 1.0f);
}
__device__ __forceinline__ float artanh_fast(float v) {
    v = fminf(fmaxf(v, -1.0f + 1e-7f), 1.0f - 1e-7f);
    return 0.5f * __logf((1.0f + v) / (1.0f - v));
}

__device__ __forceinline__ uint32_t to_tf32(float f) {
    uint32_t r; asm("cvt.rna.tf32.f32 %0, %1;" : "=r"(r) : "f"(f)); return r;
}
__device__ __forceinline__ void mma_tf32(float4& d,
    uint32_t a0, uint32_t a1, uint32_t a2, uint32_t a3,
    uint32_t b0, uint32_t b1) {
    asm volatile(
        "mma.sync.aligned.m16n8k8.row.col.f32.tf32.tf32.f32 "
        "{%0,%1,%2,%3}, {%4,%5,%6,%7}, {%8,%9}, {%0,%1,%2,%3};"
        : "+f"(d.x), "+f"(d.y), "+f"(d.z), "+f"(d.w)
        : "r"(a0), "r"(a1), "r"(a2), "r"(a3), "r"(b0), "r"(b1));
}

// --- 1. fused tf32 GEMM + row-wise epilogues ----------------------------------
#define BM 64
#define BK 32
#define SA 68   // As[row][k] stride: frag loads bank = 4g+t -> conflict-free
#define SB 72   // Bs[k][n]  stride: frag loads bank = 8t+g -> conflict-free

__global__ void __launch_bounds__(128)
k_gemm_fused(const float* __restrict__ X, const float* __restrict__ W,
             const float* __restrict__ bias, const float* __restrict__ cp,
             int N, int IN) {
    __shared__ uint32_t As[BM * SA];
    __shared__ uint32_t Bs[BK * SB];
    __shared__ float s_xn[BM];
    __shared__ float s_hb[FOUT];
    __shared__ float s_y2;

    int tid  = threadIdx.x;                // 128 threads, 4 warps
    int lane = tid & 31;
    int wrp  = tid >> 5;
    int block_row = blockIdx.x * BM;
    int g = lane >> 2;                     // 0..7  (mma group)
    int t = lane & 3;                      // 0..3  (mma thread-in-group)
    int wrow = wrp * 16;                   // warp's 16-row slice

    float c  = cp[0];
    float sc = sqrtf(c);

    // warp 0: hyperbolic bias hb = proj(expmap0(bias, c), c) and ||hb||^2
    if (wrp == 0) {
        float u0 = bias[lane], u1 = bias[lane + 32];
        float un = fmaxf(sqrtf(warp_sum(u0 * u0 + u1 * u1)), MIN_NORM);
        float scale = tanh_fast(sc * un) / (sc * un);
        float p0 = scale * u0, p1 = scale * u1;
        float pn = fmaxf(sqrtf(warp_sum(p0 * p0 + p1 * p1)), MIN_NORM);
        float maxn = (1.0f - BALL_EPS) / sc;
        float f = (pn > maxn) ? (maxn / pn) : 1.0f;
        s_hb[lane]      = p0 * f;
        s_hb[lane + 32] = p1 * f;
        if (lane == 0) {
            float hn = fminf(pn, maxn);
            s_y2 = hn * hn;
        }
    }

    float4 acc[8];                         // 8 n-tiles of m16n8 (warp covers 16x64)
    #pragma unroll
    for (int i = 0; i < 8; i++) acc[i] = make_float4(0.f, 0.f, 0.f, 0.f);

    float xsum[4] = {0.f, 0.f, 0.f, 0.f};  // fp32 ||x||^2 partials, rows (tid>>3)+16i

    for (int k0 = 0; k0 < IN; k0 += BK) {
        // X tile: 64 rows x 32 k  (512 float4, 4/thread)
        #pragma unroll
        for (int i = 0; i < 4; i++) {
            int idx = tid + i * 128;
            int r   = idx >> 3;            // 0..63
            int c4  = idx & 7;
            int gr  = block_row + r;
            float4 v = (gr < N) ? *reinterpret_cast<const float4*>(X + (size_t)gr * IN + k0 + c4 * 4)
                                : make_float4(0.f, 0.f, 0.f, 0.f);
            xsum[i] += v.x * v.x + v.y * v.y + v.z * v.z + v.w * v.w;
            uint32_t* a = As + r * SA + c4 * 4;
            a[0] = to_tf32(v.x); a[1] = to_tf32(v.y);
            a[2] = to_tf32(v.z); a[3] = to_tf32(v.w);
        }
        // W tile: 32 k x 64 n
        #pragma unroll
        for (int i = 0; i < 4; i++) {
            int idx = tid + i * 128;
            int r   = idx >> 4;            // 0..31
            int c4  = idx & 15;
            float4 v = *reinterpret_cast<const float4*>(W + (size_t)(k0 + r) * FOUT + c4 * 4);
            uint32_t* b = Bs + r * SB + c4 * 4;
            b[0] = to_tf32(v.x); b[1] = to_tf32(v.y);
            b[2] = to_tf32(v.z); b[3] = to_tf32(v.w);
        }
        __syncthreads();

        #pragma unroll
        for (int ks = 0; ks < BK / 8; ks++) {
            int kk = ks * 8;
            uint32_t a0 = As[(wrow + g)     * SA + kk + t];
            uint32_t a1 = As[(wrow + g + 8) * SA + kk + t];
            uint32_t a2 = As[(wrow + g)     * SA + kk + t + 4];
            uint32_t a3 = As[(wrow + g + 8) * SA + kk + t + 4];
            #pragma unroll
            for (int nt = 0; nt < 8; nt++) {
                uint32_t b0 = Bs[(kk + t)     * SB + nt * 8 + g];
                uint32_t b1 = Bs[(kk + t + 4) * SB + nt * 8 + g];
                mma_tf32(acc[nt], a0, a1, a2, a3, b0, b1);
            }
        }
        __syncthreads();
    }

    // per-row ||x|| (fp32-exact): lanes sharing tid>>3 hold row (tid>>3)+16i
    #pragma unroll
    for (int i = 0; i < 4; i++) {
        float s = red8(xsum[i]);
        if ((tid & 7) == 0) s_xn[(tid >> 3) + 16 * i] = fmaxf(sqrtf(s), MIN_NORM);
    }

    // zero accumulator rows for this block
    {
        float4 z = make_float4(0.f, 0.f, 0.f, 0.f);
        float4* ab = reinterpret_cast<float4*>(g_accum + (size_t)block_row * FOUT);
        int lim4 = ((N - block_row) < BM ? (N - block_row) : BM) * FOUT / 4;
        #pragma unroll
        for (int i = 0; i < (BM * FOUT / 4) / 128; i++) {
            int idx = tid + i * 128;
            if (idx < lim4) ab[idx] = z;
        }
    }
    __syncthreads();

    // epilogue in registers. Thread owns rows (wrow+g) [acc .x.y] and
    // (wrow+g+8) [acc .z.w]; row's 64 cols live in its 4-lane quad.
    float y2 = s_y2;
    float h0[8], h1[8];
    #pragma unroll
    for (int nt = 0; nt < 8; nt++) {
        h0[nt] = s_hb[nt * 8 + 2 * t];
        h1[nt] = s_hb[nt * 8 + 2 * t + 1];
    }

    float smx_a = 0.f, sxh_a = 0.f, smx_b = 0.f, sxh_b = 0.f;
    #pragma unroll
    for (int nt = 0; nt < 8; nt++) {
        smx_a += acc[nt].x * acc[nt].x + acc[nt].y * acc[nt].y;
        sxh_a += acc[nt].x * h0[nt]    + acc[nt].y * h1[nt];
        smx_b += acc[nt].z * acc[nt].z + acc[nt].w * acc[nt].w;
        sxh_b += acc[nt].z * h0[nt]    + acc[nt].w * h1[nt];
    }
    smx_a = red4(smx_a); sxh_a = red4(sxh_a);
    smx_b = red4(smx_b); sxh_b = red4(sxh_b);

    #pragma unroll
    for (int half = 0; half < 2; half++) {
        int r   = wrow + g + 8 * half;
        int row = block_row + r;
        float smx = half ? smx_b : smx_a;
        float sxh = half ? sxh_b : sxh_a;

        float x_n = s_xn[r];
        float mxn = fmaxf(sqrtf(smx), MIN_NORM);
        float at  = artanh_fast(sc * x_n);
        float scl = tanh_fast(mxn / x_n * at) / (mxn * sc);
        if (smx == 0.0f) scl = 0.0f;

        float x2 = scl * scl * smx;        // ||res||^2
        float xy = scl * sxh;              // res . hb

        float A = 1.0f + 2.0f * c * xy + c * y2;
        float B = 1.0f - c * x2;
        float den = fmaxf(1.0f + 2.0f * c * xy + c * c * x2 * y2, MIN_NORM);
        float inv_den = 1.0f / den;

        float a0[8], a1[8], pa = 0.f;
        #pragma unroll
        for (int nt = 0; nt < 8; nt++) {
            float m0 = half ? acc[nt].z : acc[nt].x;
            float m1 = half ? acc[nt].w : acc[nt].y;
            a0[nt] = (A * (scl * m0) + B * h0[nt]) * inv_den;
            a1[nt] = (A * (scl * m1) + B * h1[nt]) * inv_den;
            pa += a0[nt] * a0[nt] + a1[nt] * a1[nt];
        }
        pa = red4(pa);
        float pn = fmaxf(sqrtf(pa), MIN_NORM);
        float tt = artanh_fast(sc * pn) / (sc * pn);

        if (row < N) {
            float* dst = g_tmp + (size_t)row * FOUT + 2 * t;
            #pragma unroll
            for (int nt = 0; nt < 8; nt++)
                *reinterpret_cast<float2*>(dst + nt * 8) = make_float2(tt * a0[nt], tt * a1[nt]);
        }
    }
}

// --- 2. SpMM: accum[row[e]] += vals[e] * tmp[col[e]] --------------------------
__global__ void k_spmm(const float* __restrict__ vals, const int* __restrict__ row,
                       const int* __restrict__ col, int E) {
    int g = blockIdx.x * blockDim.x + threadIdx.x;
    int e = g >> 4;
    int lane = g & 15;
    if (e >= E) return;
    int cc = __ldg(col + e);
    int rr = __ldg(row + e);
    float v = __ldg(vals + e);
    float4 t = *reinterpret_cast<const float4*>(g_tmp + (size_t)cc * FOUT + lane * 4);
    float4 a = make_float4(t.x * v, t.y * v, t.z * v, t.w * v);
    atomicAdd(reinterpret_cast<float4*>(g_accum + (size_t)rr * FOUT) + lane, a);
}

// --- 3. final: out = proj(expmap0(accum)) ------------------------------------
__global__ void k_final(const float* __restrict__ cp, float* __restrict__ out, int N) {
    int warp = (blockIdx.x * blockDim.x + threadIdx.x) >> 5;
    int lane = threadIdx.x & 31;
    if (warp >= N) return;
    float c = cp[0];
    float sc = sqrtf(c);
    size_t base = (size_t)warp * FOUT;
    float u0 = g_accum[base + lane];
    float u1 = g_accum[base + lane + 32];
    float un = fmaxf(sqrtf(warp_sum(u0 * u0 + u1 * u1)), MIN_NORM);
    float scale = tanh_fast(sc * un) / (sc * un);
    float p0 = scale * u0, p1 = scale * u1;
    float pn = fmaxf(sqrtf(warp_sum(p0 * p0 + p1 * p1)), MIN_NORM);
    float maxn = (1.0f - BALL_EPS) / sc;
    float f = (pn > maxn) ? (maxn / pn) : 1.0f;
    out[base + lane]      = p0 * f;
    out[base + lane + 32] = p1 * f;
}

// ---------------------------------------------------------------------------

extern "C" void kernel_launch(void* const* d_in, const int* in_sizes, int n_in,
                              void* d_out, int out_size) {
    const float* x    = (const float*)d_in[0];
    const float* w    = (const float*)d_in[1];
    const float* bias = (const float*)d_in[2];
    const float* vals = (const float*)d_in[3];
    const float* c    = (const float*)d_in[4];
    const int*   row  = (const int*)d_in[5];
    const int*   col  = (const int*)d_in[6];
    float* out = (float*)d_out;

    int OUT = in_sizes[2];               // 64
    int IN  = in_sizes[1] / OUT;         // 256
    int N   = in_sizes[0] / IN;          // 50000
    int E   = in_sizes[3];               // 800000
    (void)OUT; (void)n_in; (void)out_size;

    // 1. fused tf32 GEMM + epilogues (+ accumulator zeroing)
    k_gemm_fused<<<(N + BM - 1) / BM, 128>>>(x, w, bias, c, N, IN);

    // 2. SpMM scatter-add
    long long tot = (long long)E * 16;
    k_spmm<<<(int)((tot + 255) / 256), 256>>>(vals, row, col, E);

    // 3. final expmap0 + proj
    int rowBlocks = (N + 7) / 8;
    k_final<<<rowBlocks, 256>>>(c, out, N);
}